// round 14
// baseline (speedup 1.0000x reference)
#include <cuda_runtime.h>
#include <cuda_bf16.h>
#include <cstdint>

#define D      1024
#define NTOK   2048
#define VOCAB  50257
#define VPAD   50304
#define NLAYER 12
#define NBLK   16

#define BM 128
#define BM_L 64
#define BN 64
#define BK 32

#define L_ARR 5120
#define L_BUF 25600          // AH AM AL B0 B1 (64x40 bf16 each)
#define L_NBUF 4
#define F_BUF 30720          // AH AM (128x40) + BH BL (64x40)
#define F_NBUF 3

// ---------------- scratch ----------------
__device__ float g_xbuf[2][NTOK * D];
__device__ float g_p[NTOK];
__device__ __nv_bfloat16 g_xs[2][3][NTOK * D];
__device__ __nv_bfloat16 g_wb[(size_t)NLAYER * 2 * D * D];
__device__ __nv_bfloat16 g_wp2[2][(size_t)VPAD * D];

// ---------------------------------------------------------------- helpers

__device__ __forceinline__ void mma16816(float* c, const uint32_t* a, const uint32_t* b) {
    asm volatile(
        "mma.sync.aligned.m16n8k16.row.col.f32.bf16.bf16.f32 "
        "{%0,%1,%2,%3}, {%4,%5,%6,%7}, {%8,%9}, {%0,%1,%2,%3};"
        : "+f"(c[0]), "+f"(c[1]), "+f"(c[2]), "+f"(c[3])
        : "r"(a[0]), "r"(a[1]), "r"(a[2]), "r"(a[3]), "r"(b[0]), "r"(b[1]));
}

__device__ __forceinline__ uint32_t smem_u32(const void* p) {
    uint32_t a;
    asm("{ .reg .u64 t; cvta.to.shared.u64 t, %1; cvt.u32.u64 %0, t; }" : "=r"(a) : "l"(p));
    return a;
}

__device__ __forceinline__ void ldsm_x4(uint32_t& r0, uint32_t& r1, uint32_t& r2, uint32_t& r3,
                                        uint32_t addr) {
    asm volatile("ldmatrix.sync.aligned.m8n8.x4.shared.b16 {%0,%1,%2,%3}, [%4];"
                 : "=r"(r0), "=r"(r1), "=r"(r2), "=r"(r3) : "r"(addr));
}

__device__ __forceinline__ void cpa16(uint32_t smaddr, const void* g) {
    asm volatile("cp.async.ca.shared.global [%0], [%1], 16;" :: "r"(smaddr), "l"(g) : "memory");
}
#define CP_COMMIT() asm volatile("cp.async.commit_group;" ::: "memory")
#define CP_WAIT2()  asm volatile("cp.async.wait_group 2;" ::: "memory")
#define CP_WAIT1()  asm volatile("cp.async.wait_group 1;" ::: "memory")
#define CP_WAIT0()  asm volatile("cp.async.wait_group 0;" ::: "memory")

__device__ __forceinline__ void split3(float x, __nv_bfloat16& h, __nv_bfloat16& m, __nv_bfloat16& l) {
    h = __float2bfloat16(x);
    float r1 = x - __bfloat162float(h);
    m = __float2bfloat16(r1);
    float r2 = r1 - __bfloat162float(m);
    l = __float2bfloat16(r2);
}

__device__ __forceinline__ void split2(float x, __nv_bfloat16& h, __nv_bfloat16& l) {
    h = __float2bfloat16(x);
    l = __float2bfloat16(x - __bfloat162float(h));
}

__device__ __forceinline__ uint32_t pack_bf2(__nv_bfloat16 a, __nv_bfloat16 b) {
    __nv_bfloat162 t(a, b);
    return *reinterpret_cast<uint32_t*>(&t);
}

// ---------------------------------------------------------------- pre-convert

__global__ void conv_w_kernel(const float* __restrict__ w0, const float* __restrict__ w1) {
    size_t t = (size_t)blockIdx.x * 256 + threadIdx.x;
    size_t e = t * 4;
    int l = (int)(e >> 20);
    size_t off = e & 1048575;
    float4 v0 = *reinterpret_cast<const float4*>(w0 + e);
    float4 v1 = *reinterpret_cast<const float4*>(w1 + e);
    uint2 p0, p1;
    p0.x = pack_bf2(__float2bfloat16(v0.x), __float2bfloat16(v0.y));
    p0.y = pack_bf2(__float2bfloat16(v0.z), __float2bfloat16(v0.w));
    p1.x = pack_bf2(__float2bfloat16(v1.x), __float2bfloat16(v1.y));
    p1.y = pack_bf2(__float2bfloat16(v1.z), __float2bfloat16(v1.w));
    __nv_bfloat16* d0 = g_wb + (size_t)l * 2097152 + off;
    *reinterpret_cast<uint2*>(d0) = p0;
    *reinterpret_cast<uint2*>(d0 + 1048576) = p1;
}

__global__ void conv_wp_kernel(const float* __restrict__ wp) {
    size_t t = (size_t)blockIdx.x * 256 + threadIdx.x;
    size_t e = t * 4;
    size_t row = e >> 10;
    float4 v = make_float4(0.f, 0.f, 0.f, 0.f);
    if (row < VOCAB) v = *reinterpret_cast<const float4*>(wp + e);
    __nv_bfloat16 h0, l0, h1, l1, h2, l2, h3, l3;
    split2(v.x, h0, l0); split2(v.y, h1, l1); split2(v.z, h2, l2); split2(v.w, h3, l3);
    uint2 ph, pl;
    ph.x = pack_bf2(h0, h1); ph.y = pack_bf2(h2, h3);
    pl.x = pack_bf2(l0, l1); pl.y = pack_bf2(l2, l3);
    *reinterpret_cast<uint2*>(&g_wp2[0][e]) = ph;
    *reinterpret_cast<uint2*>(&g_wp2[1][e]) = pl;
}

// ---------------------------------------------------------------- embed / router

__global__ void embed_kernel(const int* __restrict__ ids, const float* __restrict__ emb) {
    int n = blockIdx.x;
    int tid = threadIdx.x;
    int id = ids[n];
    float4 v = reinterpret_cast<const float4*>(emb + (size_t)id * D)[tid];
    reinterpret_cast<float4*>(&g_xbuf[0][(size_t)n * D])[tid] = v;
    __nv_bfloat16 h0, m0, l0, h1, m1, l1, h2, m2, l2, h3, m3, l3;
    split3(v.x, h0, m0, l0); split3(v.y, h1, m1, l1);
    split3(v.z, h2, m2, l2); split3(v.w, h3, m3, l3);
    size_t e = (size_t)n * D + tid * 4;
    uint2 p;
    p.x = pack_bf2(h0, h1); p.y = pack_bf2(h2, h3);
    *reinterpret_cast<uint2*>(&g_xs[0][0][e]) = p;
    p.x = pack_bf2(m0, m1); p.y = pack_bf2(m2, m3);
    *reinterpret_cast<uint2*>(&g_xs[0][1][e]) = p;
    p.x = pack_bf2(l0, l1); p.y = pack_bf2(l2, l3);
    *reinterpret_cast<uint2*>(&g_xs[0][2][e]) = p;
}

__global__ __launch_bounds__(256) void router_kernel(
    int par, const float* __restrict__ rw,
    const float* __restrict__ rb, float* __restrict__ probs_out)
{
    int warp = threadIdx.x >> 5, lane = threadIdx.x & 31;
    int n = blockIdx.x * 8 + warp;
    const float4* x = reinterpret_cast<const float4*>(&g_xbuf[par][(size_t)n * D]);
    const float4* w = reinterpret_cast<const float4*>(rw);
    float s = 0.f;
#pragma unroll
    for (int i = 0; i < 8; i++) {
        float4 xv = x[i * 32 + lane];
        float4 wv = __ldg(&w[i * 32 + lane]);
        s += xv.x * wv.x + xv.y * wv.y + xv.z * wv.z + xv.w * wv.w;
    }
#pragma unroll
    for (int off = 16; off > 0; off >>= 1)
        s += __shfl_xor_sync(0xFFFFFFFF, s, off);
    if (lane == 0) {
        float p = 1.f / (1.f + expf(-(s + rb[0])));
        g_p[n] = p;
        probs_out[n] = p;
    }
}

// ---------------------------------------------------------------- per-layer dual GEMM
// R11 version: 4-buffer cp.async (2 ahead), dual accumulators, fold per 64-K block.

__global__ __launch_bounds__(256, 2) void layer_gemm_kernel(
    int par, int l,
    const float* __restrict__ s0, const float* __restrict__ s1)
{
    extern __shared__ char sm[];
    const float* x_in  = g_xbuf[par];
    float*       x_out = g_xbuf[par ^ 1];
    const __nv_bfloat16* xsH = g_xs[par][0];
    const __nv_bfloat16* xsM = g_xs[par][1];
    const __nv_bfloat16* xsL = g_xs[par][2];
    __nv_bfloat16* oH = g_xs[par ^ 1][0];
    __nv_bfloat16* oM = g_xs[par ^ 1][1];
    __nv_bfloat16* oL = g_xs[par ^ 1][2];
    const __nv_bfloat16* wb = g_wb + (size_t)l * 2097152;

    uint32_t smb = smem_u32(sm);
    int tid = threadIdx.x;
    int lane = tid & 31, warp = tid >> 5;
    int wm = warp >> 1, wn = warp & 1;
    int g = lane >> 2, tg = lane & 3;
    int lrow = lane & 7, sel = lane >> 3;
    int m0 = blockIdx.y * BM_L;
    int n0 = blockIdx.x * BN;
    int rr = tid >> 2, c4 = tid & 3;

    float p0r = g_p[m0 + wm * 16 + g];
    float p1r = g_p[m0 + wm * 16 + g + 8];

    float accT[4][4];
#pragma unroll
    for (int j = 0; j < 4; j++)
#pragma unroll
        for (int q = 0; q < 4; q++) accT[j][q] = 0.f;

    auto load_tile = [&](int buf, int k0) {
        uint32_t dstb = smb + buf * L_BUF + rr * 80 + c4 * 16;
        size_t asrc = (size_t)(m0 + rr) * D + k0 + c4 * 8;
        size_t bsrc = (size_t)(n0 + rr) * D + k0 + c4 * 8;
        cpa16(dstb,             xsH + asrc);
        cpa16(dstb + 1 * L_ARR, xsM + asrc);
        cpa16(dstb + 2 * L_ARR, xsL + asrc);
        cpa16(dstb + 3 * L_ARR, wb + bsrc);
        cpa16(dstb + 4 * L_ARR, wb + 1048576 + bsrc);
    };

    load_tile(0, 0); CP_COMMIT();
    load_tile(1, BK); CP_COMMIT();

    float c0a[4][4], c1a[4][4];

    for (int ktg = 0; ktg < 32; ktg++) {
        int buf = ktg & 3;
        if (ktg + 2 < 32) { load_tile((ktg + 2) & 3, (ktg + 2) * BK); CP_COMMIT(); }
        if (ktg < 30) CP_WAIT2(); else if (ktg == 30) CP_WAIT1(); else CP_WAIT0();
        __syncthreads();

        if ((ktg & 1) == 0) {
#pragma unroll
            for (int j = 0; j < 4; j++)
#pragma unroll
                for (int q = 0; q < 4; q++) { c0a[j][q] = 0.f; c1a[j][q] = 0.f; }
        }

        uint32_t bb = smb + buf * L_BUF;
#pragma unroll
        for (int ks = 0; ks < BK; ks += 16) {
            uint32_t aoff = (uint32_t)((wm * 16 + lrow + (sel & 1) * 8) * 80 + (ks + (sel >> 1) * 8) * 2);
            uint32_t aH[4], aM[4], aL[4];
            ldsm_x4(aH[0], aH[1], aH[2], aH[3], bb + aoff);
            ldsm_x4(aM[0], aM[1], aM[2], aM[3], bb + 1 * L_ARR + aoff);
            ldsm_x4(aL[0], aL[1], aL[2], aL[3], bb + 2 * L_ARR + aoff);
            uint32_t b0[4][2], b1[4][2];
#pragma unroll
            for (int p2 = 0; p2 < 2; p2++) {
                uint32_t boff = (uint32_t)((wn * 32 + p2 * 16 + lrow + (sel >> 1) * 8) * 80 + (ks + (sel & 1) * 8) * 2);
                ldsm_x4(b0[p2*2][0], b0[p2*2][1], b0[p2*2+1][0], b0[p2*2+1][1], bb + 3 * L_ARR + boff);
                ldsm_x4(b1[p2*2][0], b1[p2*2][1], b1[p2*2+1][0], b1[p2*2+1][1], bb + 4 * L_ARR + boff);
            }
#pragma unroll
            for (int nt = 0; nt < 4; nt++) {
                mma16816(c0a[nt], aH, b0[nt]);
                mma16816(c0a[nt], aM, b0[nt]);
                mma16816(c0a[nt], aL, b0[nt]);
                mma16816(c1a[nt], aH, b1[nt]);
                mma16816(c1a[nt], aM, b1[nt]);
                mma16816(c1a[nt], aL, b1[nt]);
            }
        }

        if (ktg & 1) {
            int kb = ktg >> 1;
#pragma unroll
            for (int nt = 0; nt < 4; nt++) {
                int c = n0 + wn * 32 + nt * 8 + tg * 2;
                float sc00 = __ldg(&s0[(size_t)c * NBLK + kb]);
                float sc01 = __ldg(&s0[(size_t)(c + 1) * NBLK + kb]);
                float sc10 = __ldg(&s1[(size_t)c * NBLK + kb]);
                float sc11 = __ldg(&s1[(size_t)(c + 1) * NBLK + kb]);
                accT[nt][0] += (1.f - p0r) * sc00 * c0a[nt][0] + p0r * sc10 * c1a[nt][0];
                accT[nt][1] += (1.f - p0r) * sc01 * c0a[nt][1] + p0r * sc11 * c1a[nt][1];
                accT[nt][2] += (1.f - p1r) * sc00 * c0a[nt][2] + p1r * sc10 * c1a[nt][2];
                accT[nt][3] += (1.f - p1r) * sc01 * c0a[nt][3] + p1r * sc11 * c1a[nt][3];
            }
        }
    }

    // epilogue: x_out = x_in + accT; write 3-way splits for next stage
    {
        int r = m0 + wm * 16 + g;
#pragma unroll
        for (int nt = 0; nt < 4; nt++) {
            int c = n0 + wn * 32 + nt * 8 + tg * 2;
            size_t idx[4] = { (size_t)r * D + c, (size_t)r * D + c + 1,
                              (size_t)(r + 8) * D + c, (size_t)(r + 8) * D + c + 1 };
#pragma unroll
            for (int q = 0; q < 4; q++) {
                float xo = x_in[idx[q]] + accT[nt][q];
                x_out[idx[q]] = xo;
                __nv_bfloat16 h, m, l2;
                split3(xo, h, m, l2);
                oH[idx[q]] = h; oM[idx[q]] = m; oL[idx[q]] = l2;
            }
        }
    }
}

// ---------------------------------------------------------------- output projection
// 3 products: hH + hL + mH. 3-buffer pipeline, depth-2 in flight:
// WAIT1 -> sync -> commit(kt+2) -> compute  (G(kt+2) writes buf computed pre-sync).

__global__ __launch_bounds__(256, 2) void final_gemm_kernel(float* __restrict__ out) {
    extern __shared__ char sm[];
    const __nv_bfloat16* xH = g_xs[0][0];
    const __nv_bfloat16* xM = g_xs[0][1];
    const __nv_bfloat16* wH = g_wp2[0];
    const __nv_bfloat16* wL = g_wp2[1];

    uint32_t smb = smem_u32(sm);
    int tid = threadIdx.x;
    int lane = tid & 31, warp = tid >> 5;
    int wm = warp >> 1, wn = warp & 1;
    int g = lane >> 2, tg = lane & 3;
    int lrow = lane & 7, sel = lane >> 3;
    int m0 = blockIdx.x * BM;
    int n0 = blockIdx.y * BN;
    int rr = tid >> 2, c4 = tid & 3;

    float acc[2][4][4];
#pragma unroll
    for (int i = 0; i < 2; i++)
#pragma unroll
        for (int j = 0; j < 4; j++)
#pragma unroll
            for (int q = 0; q < 4; q++) acc[i][j][q] = 0.f;

    auto load_tile = [&](int buf, int k0) {
        uint32_t dstb = smb + buf * F_BUF + rr * 80 + c4 * 16;
        size_t a0 = (size_t)(m0 + rr) * D + k0 + c4 * 8;
        size_t a1 = (size_t)(m0 + rr + 64) * D + k0 + c4 * 8;
        size_t bsrc = (size_t)(n0 + rr) * D + k0 + c4 * 8;
        cpa16(dstb,                 xH + a0);
        cpa16(dstb + 64 * 80,       xH + a1);
        cpa16(dstb + 10240,         xM + a0);
        cpa16(dstb + 10240 + 64*80, xM + a1);
        cpa16(dstb + 20480,         wH + bsrc);
        cpa16(dstb + 25600,         wL + bsrc);
    };

    load_tile(0, 0); CP_COMMIT();
    load_tile(1, BK); CP_COMMIT();

    for (int kt = 0; kt < 32; kt++) {
        int buf = kt % 3;
        if (kt < 31) CP_WAIT1(); else CP_WAIT0();
        __syncthreads();
        if (kt + 2 < 32) {
            int nb = buf + 2; if (nb >= F_NBUF) nb -= F_NBUF;
            load_tile(nb, (kt + 2) * BK); CP_COMMIT();
        }

        uint32_t bb = smb + buf * F_BUF;
#pragma unroll
        for (int ks = 0; ks < BK; ks += 16) {
            uint32_t aH[2][4], aM[2][4];
#pragma unroll
            for (int mt = 0; mt < 2; mt++) {
                uint32_t aoff = (uint32_t)((wm * 32 + mt * 16 + lrow + (sel & 1) * 8) * 80 + (ks + (sel >> 1) * 8) * 2);
                ldsm_x4(aH[mt][0], aH[mt][1], aH[mt][2], aH[mt][3], bb + aoff);
                ldsm_x4(aM[mt][0], aM[mt][1], aM[mt][2], aM[mt][3], bb + 10240 + aoff);
            }
            uint32_t bH[4][2], bL[4][2];
#pragma unroll
            for (int p2 = 0; p2 < 2; p2++) {
                uint32_t boff = (uint32_t)((wn * 32 + p2 * 16 + lrow + (sel >> 1) * 8) * 80 + (ks + (sel & 1) * 8) * 2);
                ldsm_x4(bH[p2*2][0], bH[p2*2][1], bH[p2*2+1][0], bH[p2*2+1][1], bb + 20480 + boff);
                ldsm_x4(bL[p2*2][0], bL[p2*2][1], bL[p2*2+1][0], bL[p2*2+1][1], bb + 25600 + boff);
            }
#pragma unroll
            for (int mt = 0; mt < 2; mt++)
#pragma unroll
                for (int nt = 0; nt < 4; nt++) {
                    mma16816(acc[mt][nt], aH[mt], bH[nt]);
                    mma16816(acc[mt][nt], aH[mt], bL[nt]);
                    mma16816(acc[mt][nt], aM[mt], bH[nt]);
                }
        }
    }

#pragma unroll
    for (int mt = 0; mt < 2; mt++) {
        int r = m0 + wm * 32 + mt * 16 + g;
#pragma unroll
        for (int nt = 0; nt < 4; nt++) {
            int c = n0 + wn * 32 + nt * 8 + tg * 2;
            if (c < VOCAB)     out[(size_t)r * VOCAB + c]           = acc[mt][nt][0];
            if (c + 1 < VOCAB) out[(size_t)r * VOCAB + c + 1]       = acc[mt][nt][1];
            if (c < VOCAB)     out[(size_t)(r + 8) * VOCAB + c]     = acc[mt][nt][2];
            if (c + 1 < VOCAB) out[(size_t)(r + 8) * VOCAB + c + 1] = acc[mt][nt][3];
        }
    }
}

// ---------------------------------------------------------------- launch

extern "C" void kernel_launch(void* const* d_in, const int* in_sizes, int n_in,
                              void* d_out, int out_size) {
    const int*   ids = (const int*)d_in[0];
    const float* emb = (const float*)d_in[1];
    const float* wp  = (const float*)d_in[2];
    const float* w0  = (const float*)d_in[3];
    const float* s0  = (const float*)d_in[4];
    const float* w1  = (const float*)d_in[5];
    const float* s1  = (const float*)d_in[6];
    const float* rw  = (const float*)d_in[7];
    const float* rb  = (const float*)d_in[8];
    float* out = (float*)d_out;

    static bool attr_set = false;
    if (!attr_set) {
        cudaFuncSetAttribute(layer_gemm_kernel, cudaFuncAttributeMaxDynamicSharedMemorySize,
                             L_NBUF * L_BUF);
        cudaFuncSetAttribute(final_gemm_kernel, cudaFuncAttributeMaxDynamicSharedMemorySize,
                             F_NBUF * F_BUF);
        attr_set = true;
    }

    embed_kernel<<<NTOK, 256>>>(ids, emb);
    conv_w_kernel<<<(NLAYER * D * D / 4) / 256, 256>>>(w0, w1);

    for (int l = 0; l < NLAYER; l++) {
        int par = l & 1;
        router_kernel<<<NTOK / 8, 256>>>(par, rw + (size_t)l * D, rb + l,
                                         out + (size_t)NTOK * VOCAB + (size_t)l * NTOK);
        layer_gemm_kernel<<<dim3(D / BN, NTOK / BM_L), 256, L_NBUF * L_BUF>>>(
            par, l, s0 + (size_t)l * D * NBLK, s1 + (size_t)l * D * NBLK);
        if (l == 0)
            conv_wp_kernel<<<((size_t)VPAD * D / 4) / 256, 256>>>(wp);
    }

    final_gemm_kernel<<<dim3(NTOK / BM, VPAD / BN), 256, F_NBUF * F_BUF>>>(out);
}

// round 15
// speedup vs baseline: 1.0004x; 1.0004x over previous
#include <cuda_runtime.h>
#include <cuda_bf16.h>
#include <cstdint>

#define D      1024
#define NTOK   2048
#define VOCAB  50257
#define VPAD   50304
#define NLAYER 12
#define NBLK   16

#define BM 128
#define BM_L 64
#define BN 64
#define BK 32

#define L_ARR 5120
#define L_BUF 25600          // AH AM AL B0 B1 (64x40 bf16 each)
#define L_NBUF 4
#define F_BUF 30720          // AH AM (128x40) + BH BL (64x40)
#define F_NBUF 3

// ---------------- scratch ----------------
__device__ float g_xbuf[2][NTOK * D];
__device__ float g_p[NTOK];
__device__ __nv_bfloat16 g_xs[2][3][NTOK * D];
__device__ __nv_bfloat16 g_wb[(size_t)NLAYER * 2 * D * D];
__device__ __nv_bfloat16 g_wp2[2][(size_t)VPAD * D];

// ---------------------------------------------------------------- helpers

__device__ __forceinline__ void mma16816(float* c, const uint32_t* a, const uint32_t* b) {
    asm volatile(
        "mma.sync.aligned.m16n8k16.row.col.f32.bf16.bf16.f32 "
        "{%0,%1,%2,%3}, {%4,%5,%6,%7}, {%8,%9}, {%0,%1,%2,%3};"
        : "+f"(c[0]), "+f"(c[1]), "+f"(c[2]), "+f"(c[3])
        : "r"(a[0]), "r"(a[1]), "r"(a[2]), "r"(a[3]), "r"(b[0]), "r"(b[1]));
}

__device__ __forceinline__ uint32_t smem_u32(const void* p) {
    uint32_t a;
    asm("{ .reg .u64 t; cvta.to.shared.u64 t, %1; cvt.u32.u64 %0, t; }" : "=r"(a) : "l"(p));
    return a;
}

__device__ __forceinline__ void ldsm_x4(uint32_t& r0, uint32_t& r1, uint32_t& r2, uint32_t& r3,
                                        uint32_t addr) {
    asm volatile("ldmatrix.sync.aligned.m8n8.x4.shared.b16 {%0,%1,%2,%3}, [%4];"
                 : "=r"(r0), "=r"(r1), "=r"(r2), "=r"(r3) : "r"(addr));
}

__device__ __forceinline__ void cpa16(uint32_t smaddr, const void* g) {
    asm volatile("cp.async.ca.shared.global [%0], [%1], 16;" :: "r"(smaddr), "l"(g) : "memory");
}
#define CP_COMMIT() asm volatile("cp.async.commit_group;" ::: "memory")
#define CP_WAIT2()  asm volatile("cp.async.wait_group 2;" ::: "memory")
#define CP_WAIT1()  asm volatile("cp.async.wait_group 1;" ::: "memory")
#define CP_WAIT0()  asm volatile("cp.async.wait_group 0;" ::: "memory")

__device__ __forceinline__ void split3(float x, __nv_bfloat16& h, __nv_bfloat16& m, __nv_bfloat16& l) {
    h = __float2bfloat16(x);
    float r1 = x - __bfloat162float(h);
    m = __float2bfloat16(r1);
    float r2 = r1 - __bfloat162float(m);
    l = __float2bfloat16(r2);
}

__device__ __forceinline__ void split2(float x, __nv_bfloat16& h, __nv_bfloat16& l) {
    h = __float2bfloat16(x);
    l = __float2bfloat16(x - __bfloat162float(h));
}

__device__ __forceinline__ uint32_t pack_bf2(__nv_bfloat16 a, __nv_bfloat16 b) {
    __nv_bfloat162 t(a, b);
    return *reinterpret_cast<uint32_t*>(&t);
}

// ---------------------------------------------------------------- pre-convert

__global__ void conv_w_kernel(const float* __restrict__ w0, const float* __restrict__ w1) {
    size_t t = (size_t)blockIdx.x * 256 + threadIdx.x;
    size_t e = t * 4;
    int l = (int)(e >> 20);
    size_t off = e & 1048575;
    float4 v0 = *reinterpret_cast<const float4*>(w0 + e);
    float4 v1 = *reinterpret_cast<const float4*>(w1 + e);
    uint2 p0, p1;
    p0.x = pack_bf2(__float2bfloat16(v0.x), __float2bfloat16(v0.y));
    p0.y = pack_bf2(__float2bfloat16(v0.z), __float2bfloat16(v0.w));
    p1.x = pack_bf2(__float2bfloat16(v1.x), __float2bfloat16(v1.y));
    p1.y = pack_bf2(__float2bfloat16(v1.z), __float2bfloat16(v1.w));
    __nv_bfloat16* d0 = g_wb + (size_t)l * 2097152 + off;
    *reinterpret_cast<uint2*>(d0) = p0;
    *reinterpret_cast<uint2*>(d0 + 1048576) = p1;
}

__global__ void conv_wp_kernel(const float* __restrict__ wp) {
    size_t t = (size_t)blockIdx.x * 256 + threadIdx.x;
    size_t e = t * 4;
    size_t row = e >> 10;
    float4 v = make_float4(0.f, 0.f, 0.f, 0.f);
    if (row < VOCAB) v = *reinterpret_cast<const float4*>(wp + e);
    __nv_bfloat16 h0, l0, h1, l1, h2, l2, h3, l3;
    split2(v.x, h0, l0); split2(v.y, h1, l1); split2(v.z, h2, l2); split2(v.w, h3, l3);
    uint2 ph, pl;
    ph.x = pack_bf2(h0, h1); ph.y = pack_bf2(h2, h3);
    pl.x = pack_bf2(l0, l1); pl.y = pack_bf2(l2, l3);
    *reinterpret_cast<uint2*>(&g_wp2[0][e]) = ph;
    *reinterpret_cast<uint2*>(&g_wp2[1][e]) = pl;
}

// ---------------------------------------------------------------- embed / router

__global__ void embed_kernel(const int* __restrict__ ids, const float* __restrict__ emb) {
    int n = blockIdx.x;
    int tid = threadIdx.x;
    int id = ids[n];
    float4 v = reinterpret_cast<const float4*>(emb + (size_t)id * D)[tid];
    reinterpret_cast<float4*>(&g_xbuf[0][(size_t)n * D])[tid] = v;
    __nv_bfloat16 h0, m0, l0, h1, m1, l1, h2, m2, l2, h3, m3, l3;
    split3(v.x, h0, m0, l0); split3(v.y, h1, m1, l1);
    split3(v.z, h2, m2, l2); split3(v.w, h3, m3, l3);
    size_t e = (size_t)n * D + tid * 4;
    uint2 p;
    p.x = pack_bf2(h0, h1); p.y = pack_bf2(h2, h3);
    *reinterpret_cast<uint2*>(&g_xs[0][0][e]) = p;
    p.x = pack_bf2(m0, m1); p.y = pack_bf2(m2, m3);
    *reinterpret_cast<uint2*>(&g_xs[0][1][e]) = p;
    p.x = pack_bf2(l0, l1); p.y = pack_bf2(l2, l3);
    *reinterpret_cast<uint2*>(&g_xs[0][2][e]) = p;
}

__global__ __launch_bounds__(256) void router_kernel(
    int par, const float* __restrict__ rw,
    const float* __restrict__ rb, float* __restrict__ probs_out)
{
    int warp = threadIdx.x >> 5, lane = threadIdx.x & 31;
    int n = blockIdx.x * 8 + warp;
    const float4* x = reinterpret_cast<const float4*>(&g_xbuf[par][(size_t)n * D]);
    const float4* w = reinterpret_cast<const float4*>(rw);
    float s = 0.f;
#pragma unroll
    for (int i = 0; i < 8; i++) {
        float4 xv = x[i * 32 + lane];
        float4 wv = __ldg(&w[i * 32 + lane]);
        s += xv.x * wv.x + xv.y * wv.y + xv.z * wv.z + xv.w * wv.w;
    }
#pragma unroll
    for (int off = 16; off > 0; off >>= 1)
        s += __shfl_xor_sync(0xFFFFFFFF, s, off);
    if (lane == 0) {
        float p = 1.f / (1.f + expf(-(s + rb[0])));
        g_p[n] = p;
        probs_out[n] = p;
    }
}

// ---------------------------------------------------------------- per-layer dual GEMM
// R11 version: 4-buffer cp.async (2 ahead), dual accumulators, fold per 64-K block.

__global__ __launch_bounds__(256, 2) void layer_gemm_kernel(
    int par, int l,
    const float* __restrict__ s0, const float* __restrict__ s1)
{
    extern __shared__ char sm[];
    const float* x_in  = g_xbuf[par];
    float*       x_out = g_xbuf[par ^ 1];
    const __nv_bfloat16* xsH = g_xs[par][0];
    const __nv_bfloat16* xsM = g_xs[par][1];
    const __nv_bfloat16* xsL = g_xs[par][2];
    __nv_bfloat16* oH = g_xs[par ^ 1][0];
    __nv_bfloat16* oM = g_xs[par ^ 1][1];
    __nv_bfloat16* oL = g_xs[par ^ 1][2];
    const __nv_bfloat16* wb = g_wb + (size_t)l * 2097152;

    uint32_t smb = smem_u32(sm);
    int tid = threadIdx.x;
    int lane = tid & 31, warp = tid >> 5;
    int wm = warp >> 1, wn = warp & 1;
    int g = lane >> 2, tg = lane & 3;
    int lrow = lane & 7, sel = lane >> 3;
    int m0 = blockIdx.y * BM_L;
    int n0 = blockIdx.x * BN;
    int rr = tid >> 2, c4 = tid & 3;

    float p0r = g_p[m0 + wm * 16 + g];
    float p1r = g_p[m0 + wm * 16 + g + 8];

    float accT[4][4];
#pragma unroll
    for (int j = 0; j < 4; j++)
#pragma unroll
        for (int q = 0; q < 4; q++) accT[j][q] = 0.f;

    auto load_tile = [&](int buf, int k0) {
        uint32_t dstb = smb + buf * L_BUF + rr * 80 + c4 * 16;
        size_t asrc = (size_t)(m0 + rr) * D + k0 + c4 * 8;
        size_t bsrc = (size_t)(n0 + rr) * D + k0 + c4 * 8;
        cpa16(dstb,             xsH + asrc);
        cpa16(dstb + 1 * L_ARR, xsM + asrc);
        cpa16(dstb + 2 * L_ARR, xsL + asrc);
        cpa16(dstb + 3 * L_ARR, wb + bsrc);
        cpa16(dstb + 4 * L_ARR, wb + 1048576 + bsrc);
    };

    load_tile(0, 0); CP_COMMIT();
    load_tile(1, BK); CP_COMMIT();

    float c0a[4][4], c1a[4][4];

    for (int ktg = 0; ktg < 32; ktg++) {
        int buf = ktg & 3;
        if (ktg + 2 < 32) { load_tile((ktg + 2) & 3, (ktg + 2) * BK); CP_COMMIT(); }
        if (ktg < 30) CP_WAIT2(); else if (ktg == 30) CP_WAIT1(); else CP_WAIT0();
        __syncthreads();

        if ((ktg & 1) == 0) {
#pragma unroll
            for (int j = 0; j < 4; j++)
#pragma unroll
                for (int q = 0; q < 4; q++) { c0a[j][q] = 0.f; c1a[j][q] = 0.f; }
        }

        uint32_t bb = smb + buf * L_BUF;
#pragma unroll
        for (int ks = 0; ks < BK; ks += 16) {
            uint32_t aoff = (uint32_t)((wm * 16 + lrow + (sel & 1) * 8) * 80 + (ks + (sel >> 1) * 8) * 2);
            uint32_t aH[4], aM[4], aL[4];
            ldsm_x4(aH[0], aH[1], aH[2], aH[3], bb + aoff);
            ldsm_x4(aM[0], aM[1], aM[2], aM[3], bb + 1 * L_ARR + aoff);
            ldsm_x4(aL[0], aL[1], aL[2], aL[3], bb + 2 * L_ARR + aoff);
            uint32_t b0[4][2], b1[4][2];
#pragma unroll
            for (int p2 = 0; p2 < 2; p2++) {
                uint32_t boff = (uint32_t)((wn * 32 + p2 * 16 + lrow + (sel >> 1) * 8) * 80 + (ks + (sel & 1) * 8) * 2);
                ldsm_x4(b0[p2*2][0], b0[p2*2][1], b0[p2*2+1][0], b0[p2*2+1][1], bb + 3 * L_ARR + boff);
                ldsm_x4(b1[p2*2][0], b1[p2*2][1], b1[p2*2+1][0], b1[p2*2+1][1], bb + 4 * L_ARR + boff);
            }
#pragma unroll
            for (int nt = 0; nt < 4; nt++) {
                mma16816(c0a[nt], aH, b0[nt]);
                mma16816(c0a[nt], aM, b0[nt]);
                mma16816(c0a[nt], aL, b0[nt]);
                mma16816(c1a[nt], aH, b1[nt]);
                mma16816(c1a[nt], aM, b1[nt]);
                mma16816(c1a[nt], aL, b1[nt]);
            }
        }

        if (ktg & 1) {
            int kb = ktg >> 1;
#pragma unroll
            for (int nt = 0; nt < 4; nt++) {
                int c = n0 + wn * 32 + nt * 8 + tg * 2;
                float sc00 = __ldg(&s0[(size_t)c * NBLK + kb]);
                float sc01 = __ldg(&s0[(size_t)(c + 1) * NBLK + kb]);
                float sc10 = __ldg(&s1[(size_t)c * NBLK + kb]);
                float sc11 = __ldg(&s1[(size_t)(c + 1) * NBLK + kb]);
                accT[nt][0] += (1.f - p0r) * sc00 * c0a[nt][0] + p0r * sc10 * c1a[nt][0];
                accT[nt][1] += (1.f - p0r) * sc01 * c0a[nt][1] + p0r * sc11 * c1a[nt][1];
                accT[nt][2] += (1.f - p1r) * sc00 * c0a[nt][2] + p1r * sc10 * c1a[nt][2];
                accT[nt][3] += (1.f - p1r) * sc01 * c0a[nt][3] + p1r * sc11 * c1a[nt][3];
            }
        }
    }

    // epilogue: x_out = x_in + accT; write 3-way splits for next stage
    {
        int r = m0 + wm * 16 + g;
#pragma unroll
        for (int nt = 0; nt < 4; nt++) {
            int c = n0 + wn * 32 + nt * 8 + tg * 2;
            size_t idx[4] = { (size_t)r * D + c, (size_t)r * D + c + 1,
                              (size_t)(r + 8) * D + c, (size_t)(r + 8) * D + c + 1 };
#pragma unroll
            for (int q = 0; q < 4; q++) {
                float xo = x_in[idx[q]] + accT[nt][q];
                x_out[idx[q]] = xo;
                __nv_bfloat16 h, m, l2;
                split3(xo, h, m, l2);
                oH[idx[q]] = h; oM[idx[q]] = m; oL[idx[q]] = l2;
            }
        }
    }
}

// ---------------------------------------------------------------- output projection
// 3 products: hH + hL + mH. 3-buffer pipeline, depth-2 in flight:
// WAIT1 -> sync -> commit(kt+2) -> compute  (G(kt+2) writes buf computed pre-sync).

__global__ __launch_bounds__(256, 2) void final_gemm_kernel(float* __restrict__ out) {
    extern __shared__ char sm[];
    const __nv_bfloat16* xH = g_xs[0][0];
    const __nv_bfloat16* xM = g_xs[0][1];
    const __nv_bfloat16* wH = g_wp2[0];
    const __nv_bfloat16* wL = g_wp2[1];

    uint32_t smb = smem_u32(sm);
    int tid = threadIdx.x;
    int lane = tid & 31, warp = tid >> 5;
    int wm = warp >> 1, wn = warp & 1;
    int g = lane >> 2, tg = lane & 3;
    int lrow = lane & 7, sel = lane >> 3;
    int m0 = blockIdx.x * BM;
    int n0 = blockIdx.y * BN;
    int rr = tid >> 2, c4 = tid & 3;

    float acc[2][4][4];
#pragma unroll
    for (int i = 0; i < 2; i++)
#pragma unroll
        for (int j = 0; j < 4; j++)
#pragma unroll
            for (int q = 0; q < 4; q++) acc[i][j][q] = 0.f;

    auto load_tile = [&](int buf, int k0) {
        uint32_t dstb = smb + buf * F_BUF + rr * 80 + c4 * 16;
        size_t a0 = (size_t)(m0 + rr) * D + k0 + c4 * 8;
        size_t a1 = (size_t)(m0 + rr + 64) * D + k0 + c4 * 8;
        size_t bsrc = (size_t)(n0 + rr) * D + k0 + c4 * 8;
        cpa16(dstb,                 xH + a0);
        cpa16(dstb + 64 * 80,       xH + a1);
        cpa16(dstb + 10240,         xM + a0);
        cpa16(dstb + 10240 + 64*80, xM + a1);
        cpa16(dstb + 20480,         wH + bsrc);
        cpa16(dstb + 25600,         wL + bsrc);
    };

    load_tile(0, 0); CP_COMMIT();
    load_tile(1, BK); CP_COMMIT();

    for (int kt = 0; kt < 32; kt++) {
        int buf = kt % 3;
        if (kt < 31) CP_WAIT1(); else CP_WAIT0();
        __syncthreads();
        if (kt + 2 < 32) {
            int nb = buf + 2; if (nb >= F_NBUF) nb -= F_NBUF;
            load_tile(nb, (kt + 2) * BK); CP_COMMIT();
        }

        uint32_t bb = smb + buf * F_BUF;
#pragma unroll
        for (int ks = 0; ks < BK; ks += 16) {
            uint32_t aH[2][4], aM[2][4];
#pragma unroll
            for (int mt = 0; mt < 2; mt++) {
                uint32_t aoff = (uint32_t)((wm * 32 + mt * 16 + lrow + (sel & 1) * 8) * 80 + (ks + (sel >> 1) * 8) * 2);
                ldsm_x4(aH[mt][0], aH[mt][1], aH[mt][2], aH[mt][3], bb + aoff);
                ldsm_x4(aM[mt][0], aM[mt][1], aM[mt][2], aM[mt][3], bb + 10240 + aoff);
            }
            uint32_t bH[4][2], bL[4][2];
#pragma unroll
            for (int p2 = 0; p2 < 2; p2++) {
                uint32_t boff = (uint32_t)((wn * 32 + p2 * 16 + lrow + (sel >> 1) * 8) * 80 + (ks + (sel & 1) * 8) * 2);
                ldsm_x4(bH[p2*2][0], bH[p2*2][1], bH[p2*2+1][0], bH[p2*2+1][1], bb + 20480 + boff);
                ldsm_x4(bL[p2*2][0], bL[p2*2][1], bL[p2*2+1][0], bL[p2*2+1][1], bb + 25600 + boff);
            }
#pragma unroll
            for (int mt = 0; mt < 2; mt++)
#pragma unroll
                for (int nt = 0; nt < 4; nt++) {
                    mma16816(acc[mt][nt], aH[mt], bH[nt]);
                    mma16816(acc[mt][nt], aH[mt], bL[nt]);
                    mma16816(acc[mt][nt], aM[mt], bH[nt]);
                }
        }
    }

#pragma unroll
    for (int mt = 0; mt < 2; mt++) {
        int r = m0 + wm * 32 + mt * 16 + g;
#pragma unroll
        for (int nt = 0; nt < 4; nt++) {
            int c = n0 + wn * 32 + nt * 8 + tg * 2;
            if (c < VOCAB)     out[(size_t)r * VOCAB + c]           = acc[mt][nt][0];
            if (c + 1 < VOCAB) out[(size_t)r * VOCAB + c + 1]       = acc[mt][nt][1];
            if (c < VOCAB)     out[(size_t)(r + 8) * VOCAB + c]     = acc[mt][nt][2];
            if (c + 1 < VOCAB) out[(size_t)(r + 8) * VOCAB + c + 1] = acc[mt][nt][3];
        }
    }
}

// ---------------------------------------------------------------- launch

extern "C" void kernel_launch(void* const* d_in, const int* in_sizes, int n_in,
                              void* d_out, int out_size) {
    const int*   ids = (const int*)d_in[0];
    const float* emb = (const float*)d_in[1];
    const float* wp  = (const float*)d_in[2];
    const float* w0  = (const float*)d_in[3];
    const float* s0  = (const float*)d_in[4];
    const float* w1  = (const float*)d_in[5];
    const float* s1  = (const float*)d_in[6];
    const float* rw  = (const float*)d_in[7];
    const float* rb  = (const float*)d_in[8];
    float* out = (float*)d_out;

    static bool attr_set = false;
    if (!attr_set) {
        cudaFuncSetAttribute(layer_gemm_kernel, cudaFuncAttributeMaxDynamicSharedMemorySize,
                             L_NBUF * L_BUF);
        cudaFuncSetAttribute(final_gemm_kernel, cudaFuncAttributeMaxDynamicSharedMemorySize,
                             F_NBUF * F_BUF);
        attr_set = true;
    }

    embed_kernel<<<NTOK, 256>>>(ids, emb);
    conv_w_kernel<<<(NLAYER * D * D / 4) / 256, 256>>>(w0, w1);

    for (int l = 0; l < NLAYER; l++) {
        int par = l & 1;
        router_kernel<<<NTOK / 8, 256>>>(par, rw + (size_t)l * D, rb + l,
                                         out + (size_t)NTOK * VOCAB + (size_t)l * NTOK);
        layer_gemm_kernel<<<dim3(D / BN, NTOK / BM_L), 256, L_NBUF * L_BUF>>>(
            par, l, s0 + (size_t)l * D * NBLK, s1 + (size_t)l * D * NBLK);
        if (l == 0)
            conv_wp_kernel<<<((size_t)VPAD * D / 4) / 256, 256>>>(wp);
    }

    final_gemm_kernel<<<dim3(NTOK / BM, VPAD / BN), 256, F_NBUF * F_BUF>>>(out);
}

// round 16
// speedup vs baseline: 1.0775x; 1.0771x over previous
#include <cuda_runtime.h>
#include <cuda_bf16.h>
#include <cstdint>

#define D      1024
#define NTOK   2048
#define VOCAB  50257
#define VPAD   50304
#define NLAYER 12
#define NBLK   16

#define BM_L 64
#define BN 64
#define BK 32

#define L_ARR 5120
#define L_BUF 25600          // AH AM AL B0 B1 (64x40 bf16 each)
#define L_NBUF 4

// final gemm: BM2=128 x BN2=128, 512 threads
#define F2_ARR 10240         // 128 rows x 80B
#define F2_BUF 40960         // AH AM BH BL
#define F2_NBUF 3

// ---------------- scratch ----------------
__device__ float g_xbuf[2][NTOK * D];
__device__ float g_p[NTOK];
__device__ __nv_bfloat16 g_xs[2][3][NTOK * D];
__device__ __nv_bfloat16 g_wb[(size_t)NLAYER * 2 * D * D];
__device__ __nv_bfloat16 g_wp2[2][(size_t)VPAD * D];

// ---------------------------------------------------------------- helpers

__device__ __forceinline__ void mma16816(float* c, const uint32_t* a, const uint32_t* b) {
    asm volatile(
        "mma.sync.aligned.m16n8k16.row.col.f32.bf16.bf16.f32 "
        "{%0,%1,%2,%3}, {%4,%5,%6,%7}, {%8,%9}, {%0,%1,%2,%3};"
        : "+f"(c[0]), "+f"(c[1]), "+f"(c[2]), "+f"(c[3])
        : "r"(a[0]), "r"(a[1]), "r"(a[2]), "r"(a[3]), "r"(b[0]), "r"(b[1]));
}

__device__ __forceinline__ uint32_t smem_u32(const void* p) {
    uint32_t a;
    asm("{ .reg .u64 t; cvta.to.shared.u64 t, %1; cvt.u32.u64 %0, t; }" : "=r"(a) : "l"(p));
    return a;
}

__device__ __forceinline__ void ldsm_x4(uint32_t& r0, uint32_t& r1, uint32_t& r2, uint32_t& r3,
                                        uint32_t addr) {
    asm volatile("ldmatrix.sync.aligned.m8n8.x4.shared.b16 {%0,%1,%2,%3}, [%4];"
                 : "=r"(r0), "=r"(r1), "=r"(r2), "=r"(r3) : "r"(addr));
}

__device__ __forceinline__ void cpa16(uint32_t smaddr, const void* g) {
    asm volatile("cp.async.ca.shared.global [%0], [%1], 16;" :: "r"(smaddr), "l"(g) : "memory");
}
#define CP_COMMIT() asm volatile("cp.async.commit_group;" ::: "memory")
#define CP_WAIT2()  asm volatile("cp.async.wait_group 2;" ::: "memory")
#define CP_WAIT1()  asm volatile("cp.async.wait_group 1;" ::: "memory")
#define CP_WAIT0()  asm volatile("cp.async.wait_group 0;" ::: "memory")

__device__ __forceinline__ void split3(float x, __nv_bfloat16& h, __nv_bfloat16& m, __nv_bfloat16& l) {
    h = __float2bfloat16(x);
    float r1 = x - __bfloat162float(h);
    m = __float2bfloat16(r1);
    float r2 = r1 - __bfloat162float(m);
    l = __float2bfloat16(r2);
}

__device__ __forceinline__ void split2(float x, __nv_bfloat16& h, __nv_bfloat16& l) {
    h = __float2bfloat16(x);
    l = __float2bfloat16(x - __bfloat162float(h));
}

__device__ __forceinline__ uint32_t pack_bf2(__nv_bfloat16 a, __nv_bfloat16 b) {
    __nv_bfloat162 t(a, b);
    return *reinterpret_cast<uint32_t*>(&t);
}

// ---------------------------------------------------------------- pre-convert

__global__ void conv_w_kernel(const float* __restrict__ w0, const float* __restrict__ w1) {
    size_t t = (size_t)blockIdx.x * 256 + threadIdx.x;
    size_t e = t * 4;
    int l = (int)(e >> 20);
    size_t off = e & 1048575;
    float4 v0 = *reinterpret_cast<const float4*>(w0 + e);
    float4 v1 = *reinterpret_cast<const float4*>(w1 + e);
    uint2 p0, p1;
    p0.x = pack_bf2(__float2bfloat16(v0.x), __float2bfloat16(v0.y));
    p0.y = pack_bf2(__float2bfloat16(v0.z), __float2bfloat16(v0.w));
    p1.x = pack_bf2(__float2bfloat16(v1.x), __float2bfloat16(v1.y));
    p1.y = pack_bf2(__float2bfloat16(v1.z), __float2bfloat16(v1.w));
    __nv_bfloat16* d0 = g_wb + (size_t)l * 2097152 + off;
    *reinterpret_cast<uint2*>(d0) = p0;
    *reinterpret_cast<uint2*>(d0 + 1048576) = p1;
}

__global__ void conv_wp_kernel(const float* __restrict__ wp) {
    size_t t = (size_t)blockIdx.x * 256 + threadIdx.x;
    size_t e = t * 4;
    size_t row = e >> 10;
    float4 v = make_float4(0.f, 0.f, 0.f, 0.f);
    if (row < VOCAB) v = *reinterpret_cast<const float4*>(wp + e);
    __nv_bfloat16 h0, l0, h1, l1, h2, l2, h3, l3;
    split2(v.x, h0, l0); split2(v.y, h1, l1); split2(v.z, h2, l2); split2(v.w, h3, l3);
    uint2 ph, pl;
    ph.x = pack_bf2(h0, h1); ph.y = pack_bf2(h2, h3);
    pl.x = pack_bf2(l0, l1); pl.y = pack_bf2(l2, l3);
    *reinterpret_cast<uint2*>(&g_wp2[0][e]) = ph;
    *reinterpret_cast<uint2*>(&g_wp2[1][e]) = pl;
}

// ---------------------------------------------------------------- embed / router

__global__ void embed_kernel(const int* __restrict__ ids, const float* __restrict__ emb) {
    int n = blockIdx.x;
    int tid = threadIdx.x;
    int id = ids[n];
    float4 v = reinterpret_cast<const float4*>(emb + (size_t)id * D)[tid];
    reinterpret_cast<float4*>(&g_xbuf[0][(size_t)n * D])[tid] = v;
    __nv_bfloat16 h0, m0, l0, h1, m1, l1, h2, m2, l2, h3, m3, l3;
    split3(v.x, h0, m0, l0); split3(v.y, h1, m1, l1);
    split3(v.z, h2, m2, l2); split3(v.w, h3, m3, l3);
    size_t e = (size_t)n * D + tid * 4;
    uint2 p;
    p.x = pack_bf2(h0, h1); p.y = pack_bf2(h2, h3);
    *reinterpret_cast<uint2*>(&g_xs[0][0][e]) = p;
    p.x = pack_bf2(m0, m1); p.y = pack_bf2(m2, m3);
    *reinterpret_cast<uint2*>(&g_xs[0][1][e]) = p;
    p.x = pack_bf2(l0, l1); p.y = pack_bf2(l2, l3);
    *reinterpret_cast<uint2*>(&g_xs[0][2][e]) = p;
}

__global__ __launch_bounds__(256) void router_kernel(
    int par, const float* __restrict__ rw,
    const float* __restrict__ rb, float* __restrict__ probs_out)
{
    int warp = threadIdx.x >> 5, lane = threadIdx.x & 31;
    int n = blockIdx.x * 8 + warp;
    const float4* x = reinterpret_cast<const float4*>(&g_xbuf[par][(size_t)n * D]);
    const float4* w = reinterpret_cast<const float4*>(rw);
    float s = 0.f;
#pragma unroll
    for (int i = 0; i < 8; i++) {
        float4 xv = x[i * 32 + lane];
        float4 wv = __ldg(&w[i * 32 + lane]);
        s += xv.x * wv.x + xv.y * wv.y + xv.z * wv.z + xv.w * wv.w;
    }
#pragma unroll
    for (int off = 16; off > 0; off >>= 1)
        s += __shfl_xor_sync(0xFFFFFFFF, s, off);
    if (lane == 0) {
        float p = 1.f / (1.f + expf(-(s + rb[0])));
        g_p[n] = p;
        probs_out[n] = p;
    }
}

// ---------------------------------------------------------------- per-layer dual GEMM
// R11 version verbatim (measured 125us): 4-buffer cp.async (2 ahead), dual accumulators.

__global__ __launch_bounds__(256, 2) void layer_gemm_kernel(
    int par, int l,
    const float* __restrict__ s0, const float* __restrict__ s1)
{
    extern __shared__ char sm[];
    const float* x_in  = g_xbuf[par];
    float*       x_out = g_xbuf[par ^ 1];
    const __nv_bfloat16* xsH = g_xs[par][0];
    const __nv_bfloat16* xsM = g_xs[par][1];
    const __nv_bfloat16* xsL = g_xs[par][2];
    __nv_bfloat16* oH = g_xs[par ^ 1][0];
    __nv_bfloat16* oM = g_xs[par ^ 1][1];
    __nv_bfloat16* oL = g_xs[par ^ 1][2];
    const __nv_bfloat16* wb = g_wb + (size_t)l * 2097152;

    uint32_t smb = smem_u32(sm);
    int tid = threadIdx.x;
    int lane = tid & 31, warp = tid >> 5;
    int wm = warp >> 1, wn = warp & 1;
    int g = lane >> 2, tg = lane & 3;
    int lrow = lane & 7, sel = lane >> 3;
    int m0 = blockIdx.y * BM_L;
    int n0 = blockIdx.x * BN;
    int rr = tid >> 2, c4 = tid & 3;

    float p0r = g_p[m0 + wm * 16 + g];
    float p1r = g_p[m0 + wm * 16 + g + 8];

    float accT[4][4];
#pragma unroll
    for (int j = 0; j < 4; j++)
#pragma unroll
        for (int q = 0; q < 4; q++) accT[j][q] = 0.f;

    auto load_tile = [&](int buf, int k0) {
        uint32_t dstb = smb + buf * L_BUF + rr * 80 + c4 * 16;
        size_t asrc = (size_t)(m0 + rr) * D + k0 + c4 * 8;
        size_t bsrc = (size_t)(n0 + rr) * D + k0 + c4 * 8;
        cpa16(dstb,             xsH + asrc);
        cpa16(dstb + 1 * L_ARR, xsM + asrc);
        cpa16(dstb + 2 * L_ARR, xsL + asrc);
        cpa16(dstb + 3 * L_ARR, wb + bsrc);
        cpa16(dstb + 4 * L_ARR, wb + 1048576 + bsrc);
    };

    load_tile(0, 0); CP_COMMIT();
    load_tile(1, BK); CP_COMMIT();

    float c0a[4][4], c1a[4][4];

    for (int ktg = 0; ktg < 32; ktg++) {
        int buf = ktg & 3;
        if (ktg + 2 < 32) { load_tile((ktg + 2) & 3, (ktg + 2) * BK); CP_COMMIT(); }
        if (ktg < 30) CP_WAIT2(); else if (ktg == 30) CP_WAIT1(); else CP_WAIT0();
        __syncthreads();

        if ((ktg & 1) == 0) {
#pragma unroll
            for (int j = 0; j < 4; j++)
#pragma unroll
                for (int q = 0; q < 4; q++) { c0a[j][q] = 0.f; c1a[j][q] = 0.f; }
        }

        uint32_t bb = smb + buf * L_BUF;
#pragma unroll
        for (int ks = 0; ks < BK; ks += 16) {
            uint32_t aoff = (uint32_t)((wm * 16 + lrow + (sel & 1) * 8) * 80 + (ks + (sel >> 1) * 8) * 2);
            uint32_t aH[4], aM[4], aL[4];
            ldsm_x4(aH[0], aH[1], aH[2], aH[3], bb + aoff);
            ldsm_x4(aM[0], aM[1], aM[2], aM[3], bb + 1 * L_ARR + aoff);
            ldsm_x4(aL[0], aL[1], aL[2], aL[3], bb + 2 * L_ARR + aoff);
            uint32_t b0[4][2], b1[4][2];
#pragma unroll
            for (int p2 = 0; p2 < 2; p2++) {
                uint32_t boff = (uint32_t)((wn * 32 + p2 * 16 + lrow + (sel >> 1) * 8) * 80 + (ks + (sel & 1) * 8) * 2);
                ldsm_x4(b0[p2*2][0], b0[p2*2][1], b0[p2*2+1][0], b0[p2*2+1][1], bb + 3 * L_ARR + boff);
                ldsm_x4(b1[p2*2][0], b1[p2*2][1], b1[p2*2+1][0], b1[p2*2+1][1], bb + 4 * L_ARR + boff);
            }
#pragma unroll
            for (int nt = 0; nt < 4; nt++) {
                mma16816(c0a[nt], aH, b0[nt]);
                mma16816(c0a[nt], aM, b0[nt]);
                mma16816(c0a[nt], aL, b0[nt]);
                mma16816(c1a[nt], aH, b1[nt]);
                mma16816(c1a[nt], aM, b1[nt]);
                mma16816(c1a[nt], aL, b1[nt]);
            }
        }

        if (ktg & 1) {
            int kb = ktg >> 1;
#pragma unroll
            for (int nt = 0; nt < 4; nt++) {
                int c = n0 + wn * 32 + nt * 8 + tg * 2;
                float sc00 = __ldg(&s0[(size_t)c * NBLK + kb]);
                float sc01 = __ldg(&s0[(size_t)(c + 1) * NBLK + kb]);
                float sc10 = __ldg(&s1[(size_t)c * NBLK + kb]);
                float sc11 = __ldg(&s1[(size_t)(c + 1) * NBLK + kb]);
                accT[nt][0] += (1.f - p0r) * sc00 * c0a[nt][0] + p0r * sc10 * c1a[nt][0];
                accT[nt][1] += (1.f - p0r) * sc01 * c0a[nt][1] + p0r * sc11 * c1a[nt][1];
                accT[nt][2] += (1.f - p1r) * sc00 * c0a[nt][2] + p1r * sc10 * c1a[nt][2];
                accT[nt][3] += (1.f - p1r) * sc01 * c0a[nt][3] + p1r * sc11 * c1a[nt][3];
            }
        }
    }

    {
        int r = m0 + wm * 16 + g;
#pragma unroll
        for (int nt = 0; nt < 4; nt++) {
            int c = n0 + wn * 32 + nt * 8 + tg * 2;
            size_t idx[4] = { (size_t)r * D + c, (size_t)r * D + c + 1,
                              (size_t)(r + 8) * D + c, (size_t)(r + 8) * D + c + 1 };
#pragma unroll
            for (int q = 0; q < 4; q++) {
                float xo = x_in[idx[q]] + accT[nt][q];
                x_out[idx[q]] = xo;
                __nv_bfloat16 h, m, l2;
                split3(xo, h, m, l2);
                oH[idx[q]] = h; oM[idx[q]] = m; oL[idx[q]] = l2;
            }
        }
    }
}

// ---------------------------------------------------------------- output projection
// BM2=128 x BN2=128, 512 threads (4x4 warps, 32x32 warp tiles). 3 products.
// Halves L2 traffic vs BN=64. R11 pipeline order (commit -> WAIT1 -> sync -> compute).

__global__ __launch_bounds__(512, 1) void final_gemm_kernel(float* __restrict__ out) {
    extern __shared__ char sm[];
    const __nv_bfloat16* xH = g_xs[0][0];
    const __nv_bfloat16* xM = g_xs[0][1];
    const __nv_bfloat16* wH = g_wp2[0];
    const __nv_bfloat16* wL = g_wp2[1];

    uint32_t smb = smem_u32(sm);
    int tid = threadIdx.x;
    int lane = tid & 31, warp = tid >> 5;
    int wm = warp >> 2, wn = warp & 3;          // 4m x 4n warps
    int g = lane >> 2, tg = lane & 3;
    int lrow = lane & 7, sel = lane >> 3;
    int m0 = blockIdx.x * 128;                  // x = m tiles -> same-n CTAs co-resident
    int n0 = blockIdx.y * 128;
    int rr = tid >> 2, c4 = tid & 3;            // loader: 128 rows x 4 chunks

    float acc[2][4][4];
#pragma unroll
    for (int i = 0; i < 2; i++)
#pragma unroll
        for (int j = 0; j < 4; j++)
#pragma unroll
            for (int q = 0; q < 4; q++) acc[i][j][q] = 0.f;

    auto load_tile = [&](int buf, int k0) {
        uint32_t dstb = smb + buf * F2_BUF + rr * 80 + c4 * 16;
        size_t asrc = (size_t)(m0 + rr) * D + k0 + c4 * 8;
        size_t bsrc = (size_t)(n0 + rr) * D + k0 + c4 * 8;
        cpa16(dstb,              xH + asrc);
        cpa16(dstb + 1 * F2_ARR, xM + asrc);
        cpa16(dstb + 2 * F2_ARR, wH + bsrc);
        cpa16(dstb + 3 * F2_ARR, wL + bsrc);
    };

    load_tile(0, 0); CP_COMMIT();

    int bufc = 0;
    for (int kt = 0; kt < 32; kt++) {
        if (kt + 1 < 32) {
            int nb = bufc + 1; if (nb == F2_NBUF) nb = 0;
            load_tile(nb, (kt + 1) * BK); CP_COMMIT();
            CP_WAIT1();
        } else CP_WAIT0();
        __syncthreads();

        uint32_t bb = smb + bufc * F2_BUF;
#pragma unroll
        for (int ks = 0; ks < BK; ks += 16) {
            uint32_t aH[2][4], aM[2][4];
#pragma unroll
            for (int mt = 0; mt < 2; mt++) {
                uint32_t aoff = (uint32_t)((wm * 32 + mt * 16 + lrow + (sel & 1) * 8) * 80 + (ks + (sel >> 1) * 8) * 2);
                ldsm_x4(aH[mt][0], aH[mt][1], aH[mt][2], aH[mt][3], bb + aoff);
                ldsm_x4(aM[mt][0], aM[mt][1], aM[mt][2], aM[mt][3], bb + 1 * F2_ARR + aoff);
            }
            uint32_t bH[4][2], bL[4][2];
#pragma unroll
            for (int p2 = 0; p2 < 2; p2++) {
                uint32_t boff = (uint32_t)((wn * 32 + p2 * 16 + lrow + (sel >> 1) * 8) * 80 + (ks + (sel & 1) * 8) * 2);
                ldsm_x4(bH[p2*2][0], bH[p2*2][1], bH[p2*2+1][0], bH[p2*2+1][1], bb + 2 * F2_ARR + boff);
                ldsm_x4(bL[p2*2][0], bL[p2*2][1], bL[p2*2+1][0], bL[p2*2+1][1], bb + 3 * F2_ARR + boff);
            }
#pragma unroll
            for (int mt = 0; mt < 2; mt++)
#pragma unroll
                for (int nt = 0; nt < 4; nt++) {
                    mma16816(acc[mt][nt], aH[mt], bH[nt]);
                    mma16816(acc[mt][nt], aH[mt], bL[nt]);
                    mma16816(acc[mt][nt], aM[mt], bH[nt]);
                }
        }
        bufc++; if (bufc == F2_NBUF) bufc = 0;
    }

#pragma unroll
    for (int mt = 0; mt < 2; mt++) {
        int r = m0 + wm * 32 + mt * 16 + g;
#pragma unroll
        for (int nt = 0; nt < 4; nt++) {
            int c = n0 + wn * 32 + nt * 8 + tg * 2;
            if (c < VOCAB)     out[(size_t)r * VOCAB + c]           = acc[mt][nt][0];
            if (c + 1 < VOCAB) out[(size_t)r * VOCAB + c + 1]       = acc[mt][nt][1];
            if (c < VOCAB)     out[(size_t)(r + 8) * VOCAB + c]     = acc[mt][nt][2];
            if (c + 1 < VOCAB) out[(size_t)(r + 8) * VOCAB + c + 1] = acc[mt][nt][3];
        }
    }
}

// ---------------------------------------------------------------- launch

extern "C" void kernel_launch(void* const* d_in, const int* in_sizes, int n_in,
                              void* d_out, int out_size) {
    const int*   ids = (const int*)d_in[0];
    const float* emb = (const float*)d_in[1];
    const float* wp  = (const float*)d_in[2];
    const float* w0  = (const float*)d_in[3];
    const float* s0  = (const float*)d_in[4];
    const float* w1  = (const float*)d_in[5];
    const float* s1  = (const float*)d_in[6];
    const float* rw  = (const float*)d_in[7];
    const float* rb  = (const float*)d_in[8];
    float* out = (float*)d_out;

    static bool attr_set = false;
    if (!attr_set) {
        cudaFuncSetAttribute(layer_gemm_kernel, cudaFuncAttributeMaxDynamicSharedMemorySize,
                             L_NBUF * L_BUF);
        cudaFuncSetAttribute(final_gemm_kernel, cudaFuncAttributeMaxDynamicSharedMemorySize,
                             F2_NBUF * F2_BUF);
        attr_set = true;
    }

    embed_kernel<<<NTOK, 256>>>(ids, emb);
    conv_w_kernel<<<(NLAYER * D * D / 4) / 256, 256>>>(w0, w1);

    for (int l = 0; l < NLAYER; l++) {
        int par = l & 1;
        router_kernel<<<NTOK / 8, 256>>>(par, rw + (size_t)l * D, rb + l,
                                         out + (size_t)NTOK * VOCAB + (size_t)l * NTOK);
        layer_gemm_kernel<<<dim3(D / BN, NTOK / BM_L), 256, L_NBUF * L_BUF>>>(
            par, l, s0 + (size_t)l * D * NBLK, s1 + (size_t)l * D * NBLK);
        if (l == 0)
            conv_wp_kernel<<<((size_t)VPAD * D / 4) / 256, 256>>>(wp);
    }

    final_gemm_kernel<<<dim3(NTOK / 128, VPAD / 128), 512, F2_NBUF * F2_BUF>>>(out);
}

// round 17
// speedup vs baseline: 1.0869x; 1.0087x over previous
#include <cuda_runtime.h>
#include <cuda_bf16.h>
#include <cstdint>

#define D      1024
#define NTOK   2048
#define VOCAB  50257
#define VPAD   50304
#define NLAYER 12
#define NBLK   16

#define BM_L 64
#define BN 64
#define BK 32

#define L_ARR 5120
#define L_BUF 25600          // AH AM AL B0 B1 (64x40 bf16 each)
#define L_NBUF 4

#define F2_ARR 10240         // 128 rows x 80B
#define F2_BUF 40960         // AH AM BH BL
#define F2_NBUF 3

// ---------------- scratch ----------------
__device__ float g_xbuf[2][NTOK * D];
__device__ __nv_bfloat16 g_xs[2][3][NTOK * D];
__device__ __nv_bfloat16 g_wb[(size_t)NLAYER * 2 * D * D];
__device__ __nv_bfloat16 g_wp2[2][(size_t)VPAD * D];
__device__ float g_rpart[2][NTOK * 32];      // router partial dots, 32 slots/token

// ---------------------------------------------------------------- helpers

__device__ __forceinline__ void mma16816(float* c, const uint32_t* a, const uint32_t* b) {
    asm volatile(
        "mma.sync.aligned.m16n8k16.row.col.f32.bf16.bf16.f32 "
        "{%0,%1,%2,%3}, {%4,%5,%6,%7}, {%8,%9}, {%0,%1,%2,%3};"
        : "+f"(c[0]), "+f"(c[1]), "+f"(c[2]), "+f"(c[3])
        : "r"(a[0]), "r"(a[1]), "r"(a[2]), "r"(a[3]), "r"(b[0]), "r"(b[1]));
}

__device__ __forceinline__ uint32_t smem_u32(const void* p) {
    uint32_t a;
    asm("{ .reg .u64 t; cvta.to.shared.u64 t, %1; cvt.u32.u64 %0, t; }" : "=r"(a) : "l"(p));
    return a;
}

__device__ __forceinline__ void ldsm_x4(uint32_t& r0, uint32_t& r1, uint32_t& r2, uint32_t& r3,
                                        uint32_t addr) {
    asm volatile("ldmatrix.sync.aligned.m8n8.x4.shared.b16 {%0,%1,%2,%3}, [%4];"
                 : "=r"(r0), "=r"(r1), "=r"(r2), "=r"(r3) : "r"(addr));
}

__device__ __forceinline__ void cpa16(uint32_t smaddr, const void* g) {
    asm volatile("cp.async.ca.shared.global [%0], [%1], 16;" :: "r"(smaddr), "l"(g) : "memory");
}
#define CP_COMMIT() asm volatile("cp.async.commit_group;" ::: "memory")
#define CP_WAIT2()  asm volatile("cp.async.wait_group 2;" ::: "memory")
#define CP_WAIT1()  asm volatile("cp.async.wait_group 1;" ::: "memory")
#define CP_WAIT0()  asm volatile("cp.async.wait_group 0;" ::: "memory")

__device__ __forceinline__ void split3(float x, __nv_bfloat16& h, __nv_bfloat16& m, __nv_bfloat16& l) {
    h = __float2bfloat16(x);
    float r1 = x - __bfloat162float(h);
    m = __float2bfloat16(r1);
    float r2 = r1 - __bfloat162float(m);
    l = __float2bfloat16(r2);
}

__device__ __forceinline__ void split2(float x, __nv_bfloat16& h, __nv_bfloat16& l) {
    h = __float2bfloat16(x);
    l = __float2bfloat16(x - __bfloat162float(h));
}

__device__ __forceinline__ uint32_t pack_bf2(__nv_bfloat16 a, __nv_bfloat16 b) {
    __nv_bfloat162 t(a, b);
    return *reinterpret_cast<uint32_t*>(&t);
}

// ---------------------------------------------------------------- pre-convert

__global__ void zero_rpart_kernel() {
    int t = blockIdx.x * 256 + threadIdx.x;
    float4* p = reinterpret_cast<float4*>(&g_rpart[0][0]);
    p[t] = make_float4(0.f, 0.f, 0.f, 0.f);     // 2*2048*32/4 = 32768 float4, grid 128x256
}

__global__ void conv_w_kernel(const float* __restrict__ w0, const float* __restrict__ w1) {
    size_t t = (size_t)blockIdx.x * 256 + threadIdx.x;
    size_t e = t * 4;
    int l = (int)(e >> 20);
    size_t off = e & 1048575;
    float4 v0 = *reinterpret_cast<const float4*>(w0 + e);
    float4 v1 = *reinterpret_cast<const float4*>(w1 + e);
    uint2 p0, p1;
    p0.x = pack_bf2(__float2bfloat16(v0.x), __float2bfloat16(v0.y));
    p0.y = pack_bf2(__float2bfloat16(v0.z), __float2bfloat16(v0.w));
    p1.x = pack_bf2(__float2bfloat16(v1.x), __float2bfloat16(v1.y));
    p1.y = pack_bf2(__float2bfloat16(v1.z), __float2bfloat16(v1.w));
    __nv_bfloat16* d0 = g_wb + (size_t)l * 2097152 + off;
    *reinterpret_cast<uint2*>(d0) = p0;
    *reinterpret_cast<uint2*>(d0 + 1048576) = p1;
}

__global__ void conv_wp_kernel(const float* __restrict__ wp) {
    size_t t = (size_t)blockIdx.x * 256 + threadIdx.x;
    size_t e = t * 4;
    size_t row = e >> 10;
    float4 v = make_float4(0.f, 0.f, 0.f, 0.f);
    if (row < VOCAB) v = *reinterpret_cast<const float4*>(wp + e);
    __nv_bfloat16 h0, l0, h1, l1, h2, l2, h3, l3;
    split2(v.x, h0, l0); split2(v.y, h1, l1); split2(v.z, h2, l2); split2(v.w, h3, l3);
    uint2 ph, pl;
    ph.x = pack_bf2(h0, h1); ph.y = pack_bf2(h2, h3);
    pl.x = pack_bf2(l0, l1); pl.y = pack_bf2(l2, l3);
    *reinterpret_cast<uint2*>(&g_wp2[0][e]) = ph;
    *reinterpret_cast<uint2*>(&g_wp2[1][e]) = pl;
}

// ---------------------------------------------------------------- embed (+ layer-0 router dot)

__global__ void embed_kernel(const int* __restrict__ ids, const float* __restrict__ emb,
                             const float* __restrict__ rw0) {
    int n = blockIdx.x;
    int tid = threadIdx.x;
    int id = ids[n];
    float4 v = reinterpret_cast<const float4*>(emb + (size_t)id * D)[tid];
    reinterpret_cast<float4*>(&g_xbuf[0][(size_t)n * D])[tid] = v;
    __nv_bfloat16 h0, m0, l0, h1, m1, l1, h2, m2, l2, h3, m3, l3;
    split3(v.x, h0, m0, l0); split3(v.y, h1, m1, l1);
    split3(v.z, h2, m2, l2); split3(v.w, h3, m3, l3);
    size_t e = (size_t)n * D + tid * 4;
    uint2 p;
    p.x = pack_bf2(h0, h1); p.y = pack_bf2(h2, h3);
    *reinterpret_cast<uint2*>(&g_xs[0][0][e]) = p;
    p.x = pack_bf2(m0, m1); p.y = pack_bf2(m2, m3);
    *reinterpret_cast<uint2*>(&g_xs[0][1][e]) = p;
    p.x = pack_bf2(l0, l1); p.y = pack_bf2(l2, l3);
    *reinterpret_cast<uint2*>(&g_xs[0][2][e]) = p;

    // router dot for layer 0
    float4 wv = __ldg(&reinterpret_cast<const float4*>(rw0)[tid]);
    float s = v.x * wv.x + v.y * wv.y + v.z * wv.z + v.w * wv.w;
    __shared__ float red[256];
    red[tid] = s;
    __syncthreads();
    for (int off = 128; off > 0; off >>= 1) {
        if (tid < off) red[tid] += red[tid + off];
        __syncthreads();
    }
    if (tid == 0) g_rpart[0][(size_t)n * 32] = red[0];
}

// ---------------------------------------------------------------- per-layer dual GEMM
// R11 mainloop (measured best). Router fused: prologue sums 32 partial-dot slots ->
// sigmoid -> probs_out; epilogue computes next layer's partial dots (deterministic slots).

__global__ __launch_bounds__(256, 2) void layer_gemm_kernel(
    int par, int l,
    const float* __restrict__ s0, const float* __restrict__ s1,
    const float* __restrict__ rb_l, const float* __restrict__ rw_next,
    float* __restrict__ probs_out)
{
    extern __shared__ char sm[];
    const float* x_in  = g_xbuf[par];
    float*       x_out = g_xbuf[par ^ 1];
    const __nv_bfloat16* xsH = g_xs[par][0];
    const __nv_bfloat16* xsM = g_xs[par][1];
    const __nv_bfloat16* xsL = g_xs[par][2];
    __nv_bfloat16* oH = g_xs[par ^ 1][0];
    __nv_bfloat16* oM = g_xs[par ^ 1][1];
    __nv_bfloat16* oL = g_xs[par ^ 1][2];
    const __nv_bfloat16* wb = g_wb + (size_t)l * 2097152;

    uint32_t smb = smem_u32(sm);
    int tid = threadIdx.x;
    int lane = tid & 31, warp = tid >> 5;
    int wm = warp >> 1, wn = warp & 1;
    int g = lane >> 2, tg = lane & 3;
    int lrow = lane & 7, sel = lane >> 3;
    int m0 = blockIdx.y * BM_L;
    int n0 = blockIdx.x * BN;
    int rr = tid >> 2, c4 = tid & 3;

    // ---- fused router prologue ----
    int r0 = m0 + wm * 16 + g;
    float p0r, p1r;
    {
        const float* rp = g_rpart[l & 1];
        float rb_v = __ldg(rb_l);
        float sA = 0.f, sB = 0.f;
        const float4* rpA = reinterpret_cast<const float4*>(rp + (size_t)r0 * 32);
        const float4* rpB = reinterpret_cast<const float4*>(rp + (size_t)(r0 + 8) * 32);
#pragma unroll
        for (int i = 0; i < 8; i++) {
            float4 a = __ldg(&rpA[i]); sA += (a.x + a.y) + (a.z + a.w);
            float4 b = __ldg(&rpB[i]); sB += (b.x + b.y) + (b.z + b.w);
        }
        p0r = 1.f / (1.f + expf(-(sA + rb_v)));
        p1r = 1.f / (1.f + expf(-(sB + rb_v)));
        if (blockIdx.x == 0 && wn == 0 && tg == 0) {
            probs_out[r0] = p0r;
            probs_out[r0 + 8] = p1r;
        }
    }

    float accT[4][4];
#pragma unroll
    for (int j = 0; j < 4; j++)
#pragma unroll
        for (int q = 0; q < 4; q++) accT[j][q] = 0.f;

    auto load_tile = [&](int buf, int k0) {
        uint32_t dstb = smb + buf * L_BUF + rr * 80 + c4 * 16;
        size_t asrc = (size_t)(m0 + rr) * D + k0 + c4 * 8;
        size_t bsrc = (size_t)(n0 + rr) * D + k0 + c4 * 8;
        cpa16(dstb,             xsH + asrc);
        cpa16(dstb + 1 * L_ARR, xsM + asrc);
        cpa16(dstb + 2 * L_ARR, xsL + asrc);
        cpa16(dstb + 3 * L_ARR, wb + bsrc);
        cpa16(dstb + 4 * L_ARR, wb + 1048576 + bsrc);
    };

    load_tile(0, 0); CP_COMMIT();
    load_tile(1, BK); CP_COMMIT();

    float c0a[4][4], c1a[4][4];

    for (int ktg = 0; ktg < 32; ktg++) {
        int buf = ktg & 3;
        if (ktg + 2 < 32) { load_tile((ktg + 2) & 3, (ktg + 2) * BK); CP_COMMIT(); }
        if (ktg < 30) CP_WAIT2(); else if (ktg == 30) CP_WAIT1(); else CP_WAIT0();
        __syncthreads();

        if ((ktg & 1) == 0) {
#pragma unroll
            for (int j = 0; j < 4; j++)
#pragma unroll
                for (int q = 0; q < 4; q++) { c0a[j][q] = 0.f; c1a[j][q] = 0.f; }
        }

        uint32_t bb = smb + buf * L_BUF;
#pragma unroll
        for (int ks = 0; ks < BK; ks += 16) {
            uint32_t aoff = (uint32_t)((wm * 16 + lrow + (sel & 1) * 8) * 80 + (ks + (sel >> 1) * 8) * 2);
            uint32_t aH[4], aM[4], aL[4];
            ldsm_x4(aH[0], aH[1], aH[2], aH[3], bb + aoff);
            ldsm_x4(aM[0], aM[1], aM[2], aM[3], bb + 1 * L_ARR + aoff);
            ldsm_x4(aL[0], aL[1], aL[2], aL[3], bb + 2 * L_ARR + aoff);
            uint32_t b0[4][2], b1[4][2];
#pragma unroll
            for (int p2 = 0; p2 < 2; p2++) {
                uint32_t boff = (uint32_t)((wn * 32 + p2 * 16 + lrow + (sel >> 1) * 8) * 80 + (ks + (sel & 1) * 8) * 2);
                ldsm_x4(b0[p2*2][0], b0[p2*2][1], b0[p2*2+1][0], b0[p2*2+1][1], bb + 3 * L_ARR + boff);
                ldsm_x4(b1[p2*2][0], b1[p2*2][1], b1[p2*2+1][0], b1[p2*2+1][1], bb + 4 * L_ARR + boff);
            }
            // product-major: 8 independent accs between same-acc reuses
#pragma unroll
            for (int nt = 0; nt < 4; nt++) mma16816(c0a[nt], aH, b0[nt]);
#pragma unroll
            for (int nt = 0; nt < 4; nt++) mma16816(c1a[nt], aH, b1[nt]);
#pragma unroll
            for (int nt = 0; nt < 4; nt++) mma16816(c0a[nt], aM, b0[nt]);
#pragma unroll
            for (int nt = 0; nt < 4; nt++) mma16816(c1a[nt], aM, b1[nt]);
#pragma unroll
            for (int nt = 0; nt < 4; nt++) mma16816(c0a[nt], aL, b0[nt]);
#pragma unroll
            for (int nt = 0; nt < 4; nt++) mma16816(c1a[nt], aL, b1[nt]);
        }

        if (ktg & 1) {
            int kb = ktg >> 1;
#pragma unroll
            for (int nt = 0; nt < 4; nt++) {
                int c = n0 + wn * 32 + nt * 8 + tg * 2;
                float sc00 = __ldg(&s0[(size_t)c * NBLK + kb]);
                float sc01 = __ldg(&s0[(size_t)(c + 1) * NBLK + kb]);
                float sc10 = __ldg(&s1[(size_t)c * NBLK + kb]);
                float sc11 = __ldg(&s1[(size_t)(c + 1) * NBLK + kb]);
                accT[nt][0] += (1.f - p0r) * sc00 * c0a[nt][0] + p0r * sc10 * c1a[nt][0];
                accT[nt][1] += (1.f - p0r) * sc01 * c0a[nt][1] + p0r * sc11 * c1a[nt][1];
                accT[nt][2] += (1.f - p1r) * sc00 * c0a[nt][2] + p1r * sc10 * c1a[nt][2];
                accT[nt][3] += (1.f - p1r) * sc01 * c0a[nt][3] + p1r * sc11 * c1a[nt][3];
            }
        }
    }

    // epilogue: residual add, splits for next stage, next-layer router partial dot
    {
        float pr = 0.f, pr8 = 0.f;
#pragma unroll
        for (int nt = 0; nt < 4; nt++) {
            int cidx = n0 + wn * 32 + nt * 8 + tg * 2;
            size_t idx[4] = { (size_t)r0 * D + cidx, (size_t)r0 * D + cidx + 1,
                              (size_t)(r0 + 8) * D + cidx, (size_t)(r0 + 8) * D + cidx + 1 };
            float vals[4];
            vals[0] = x_in[idx[0]] + accT[nt][0];
            vals[1] = x_in[idx[1]] + accT[nt][1];
            vals[2] = x_in[idx[2]] + accT[nt][2];
            vals[3] = x_in[idx[3]] + accT[nt][3];
#pragma unroll
            for (int q = 0; q < 4; q++) {
                x_out[idx[q]] = vals[q];
                __nv_bfloat16 h, m, l2;
                split3(vals[q], h, m, l2);
                oH[idx[q]] = h; oM[idx[q]] = m; oL[idx[q]] = l2;
            }
            if (rw_next) {
                float w0v = __ldg(&rw_next[cidx]);
                float w1v = __ldg(&rw_next[cidx + 1]);
                pr  += vals[0] * w0v + vals[1] * w1v;
                pr8 += vals[2] * w0v + vals[3] * w1v;
            }
        }
        if (rw_next) {
            pr  += __shfl_xor_sync(0xFFFFFFFF, pr, 1);
            pr  += __shfl_xor_sync(0xFFFFFFFF, pr, 2);
            pr8 += __shfl_xor_sync(0xFFFFFFFF, pr8, 1);
            pr8 += __shfl_xor_sync(0xFFFFFFFF, pr8, 2);
            if (tg == 0) {
                float* dst = g_rpart[(l + 1) & 1];
                int slot = blockIdx.x * 2 + wn;
                dst[(size_t)r0 * 32 + slot] = pr;
                dst[(size_t)(r0 + 8) * 32 + slot] = pr8;
            }
        }
    }
}

// ---------------------------------------------------------------- output projection
// BM2=128 x BN2=128, 512 threads. 3 products, product-major MMA order, streaming stores.

__global__ __launch_bounds__(512, 1) void final_gemm_kernel(float* __restrict__ out) {
    extern __shared__ char sm[];
    const __nv_bfloat16* xH = g_xs[0][0];
    const __nv_bfloat16* xM = g_xs[0][1];
    const __nv_bfloat16* wH = g_wp2[0];
    const __nv_bfloat16* wL = g_wp2[1];

    uint32_t smb = smem_u32(sm);
    int tid = threadIdx.x;
    int lane = tid & 31, warp = tid >> 5;
    int wm = warp >> 2, wn = warp & 3;
    int g = lane >> 2, tg = lane & 3;
    int lrow = lane & 7, sel = lane >> 3;
    int m0 = blockIdx.x * 128;
    int n0 = blockIdx.y * 128;
    int rr = tid >> 2, c4 = tid & 3;

    float acc[2][4][4];
#pragma unroll
    for (int i = 0; i < 2; i++)
#pragma unroll
        for (int j = 0; j < 4; j++)
#pragma unroll
            for (int q = 0; q < 4; q++) acc[i][j][q] = 0.f;

    auto load_tile = [&](int buf, int k0) {
        uint32_t dstb = smb + buf * F2_BUF + rr * 80 + c4 * 16;
        size_t asrc = (size_t)(m0 + rr) * D + k0 + c4 * 8;
        size_t bsrc = (size_t)(n0 + rr) * D + k0 + c4 * 8;
        cpa16(dstb,              xH + asrc);
        cpa16(dstb + 1 * F2_ARR, xM + asrc);
        cpa16(dstb + 2 * F2_ARR, wH + bsrc);
        cpa16(dstb + 3 * F2_ARR, wL + bsrc);
    };

    load_tile(0, 0); CP_COMMIT();

    int bufc = 0;
    for (int kt = 0; kt < 32; kt++) {
        if (kt + 1 < 32) {
            int nb = bufc + 1; if (nb == F2_NBUF) nb = 0;
            load_tile(nb, (kt + 1) * BK); CP_COMMIT();
            CP_WAIT1();
        } else CP_WAIT0();
        __syncthreads();

        uint32_t bb = smb + bufc * F2_BUF;
#pragma unroll
        for (int ks = 0; ks < BK; ks += 16) {
            uint32_t aH[2][4], aM[2][4];
#pragma unroll
            for (int mt = 0; mt < 2; mt++) {
                uint32_t aoff = (uint32_t)((wm * 32 + mt * 16 + lrow + (sel & 1) * 8) * 80 + (ks + (sel >> 1) * 8) * 2);
                ldsm_x4(aH[mt][0], aH[mt][1], aH[mt][2], aH[mt][3], bb + aoff);
                ldsm_x4(aM[mt][0], aM[mt][1], aM[mt][2], aM[mt][3], bb + 1 * F2_ARR + aoff);
            }
            uint32_t bH[4][2], bL[4][2];
#pragma unroll
            for (int p2 = 0; p2 < 2; p2++) {
                uint32_t boff = (uint32_t)((wn * 32 + p2 * 16 + lrow + (sel >> 1) * 8) * 80 + (ks + (sel & 1) * 8) * 2);
                ldsm_x4(bH[p2*2][0], bH[p2*2][1], bH[p2*2+1][0], bH[p2*2+1][1], bb + 2 * F2_ARR + boff);
                ldsm_x4(bL[p2*2][0], bL[p2*2][1], bL[p2*2+1][0], bL[p2*2+1][1], bb + 3 * F2_ARR + boff);
            }
            // product-major: 8 independent accs between same-acc reuses
#pragma unroll
            for (int mt = 0; mt < 2; mt++)
#pragma unroll
                for (int nt = 0; nt < 4; nt++) mma16816(acc[mt][nt], aH[mt], bH[nt]);
#pragma unroll
            for (int mt = 0; mt < 2; mt++)
#pragma unroll
                for (int nt = 0; nt < 4; nt++) mma16816(acc[mt][nt], aH[mt], bL[nt]);
#pragma unroll
            for (int mt = 0; mt < 2; mt++)
#pragma unroll
                for (int nt = 0; nt < 4; nt++) mma16816(acc[mt][nt], aM[mt], bH[nt]);
        }
        bufc++; if (bufc == F2_NBUF) bufc = 0;
    }

#pragma unroll
    for (int mt = 0; mt < 2; mt++) {
        int r = m0 + wm * 32 + mt * 16 + g;
#pragma unroll
        for (int nt = 0; nt < 4; nt++) {
            int c = n0 + wn * 32 + nt * 8 + tg * 2;
            float* base = out + (size_t)r * VOCAB;
            float* base8 = out + (size_t)(r + 8) * VOCAB;
            if (c < VOCAB)     __stcs(base + c,      acc[mt][nt][0]);
            if (c + 1 < VOCAB) __stcs(base + c + 1,  acc[mt][nt][1]);
            if (c < VOCAB)     __stcs(base8 + c,     acc[mt][nt][2]);
            if (c + 1 < VOCAB) __stcs(base8 + c + 1, acc[mt][nt][3]);
        }
    }
}

// ---------------------------------------------------------------- launch

extern "C" void kernel_launch(void* const* d_in, const int* in_sizes, int n_in,
                              void* d_out, int out_size) {
    const int*   ids = (const int*)d_in[0];
    const float* emb = (const float*)d_in[1];
    const float* wp  = (const float*)d_in[2];
    const float* w0  = (const float*)d_in[3];
    const float* s0  = (const float*)d_in[4];
    const float* w1  = (const float*)d_in[5];
    const float* s1  = (const float*)d_in[6];
    const float* rw  = (const float*)d_in[7];
    const float* rb  = (const float*)d_in[8];
    float* out = (float*)d_out;

    static bool attr_set = false;
    if (!attr_set) {
        cudaFuncSetAttribute(layer_gemm_kernel, cudaFuncAttributeMaxDynamicSharedMemorySize,
                             L_NBUF * L_BUF);
        cudaFuncSetAttribute(final_gemm_kernel, cudaFuncAttributeMaxDynamicSharedMemorySize,
                             F2_NBUF * F2_BUF);
        attr_set = true;
    }

    zero_rpart_kernel<<<128, 256>>>();
    embed_kernel<<<NTOK, 256>>>(ids, emb, rw);
    conv_w_kernel<<<(NLAYER * D * D / 4) / 256, 256>>>(w0, w1);

    for (int l = 0; l < NLAYER; l++) {
        int par = l & 1;
        const float* rw_next = (l + 1 < NLAYER) ? (rw + (size_t)(l + 1) * D) : nullptr;
        layer_gemm_kernel<<<dim3(D / BN, NTOK / BM_L), 256, L_NBUF * L_BUF>>>(
            par, l, s0 + (size_t)l * D * NBLK, s1 + (size_t)l * D * NBLK,
            rb + l, rw_next,
            out + (size_t)NTOK * VOCAB + (size_t)l * NTOK);
        if (l == 0)
            conv_wp_kernel<<<((size_t)VPAD * D / 4) / 256, 256>>>(wp);
    }

    final_gemm_kernel<<<dim3(NTOK / 128, VPAD / 128), 512, F2_NBUF * F2_BUF>>>(out);
}